// round 1
// baseline (speedup 1.0000x reference)
#include <cuda_runtime.h>
#include <cuda_bf16.h>

// Problem dims
#define B_   2
#define S_   1024
#define HID_ 2048
#define HQ_  32
#define HKV_ 8
#define HD_  64
#define KV_  (HKV_*HD_)   // 512
#define M_   (B_*S_)      // 2048

// Scratch (device globals — no allocation allowed)
__device__ float g_q[M_*HID_];     // 16 MB
__device__ float g_k[M_*KV_];      //  4 MB
__device__ float g_v[M_*KV_];      //  4 MB
__device__ float g_att[M_*HID_];   // 16 MB

// ---------------------------------------------------------------------------
// Classic 128x128x8 SGEMM, 256 threads, 8x8 per thread. C = A[MxK] @ B[KxN]
// ---------------------------------------------------------------------------
__global__ void sgemm128(const float* __restrict__ A, const float* __restrict__ Bm,
                         float* __restrict__ C, int M, int N, int K) {
    const int BM = 128, BN = 128, BK = 8, TM = 8, TN = 8;
    __shared__ float As[BM][BK];
    __shared__ float Bs[BK][BN];

    int tid = threadIdx.x;
    int tx = tid % (BN / TN);   // 0..15
    int ty = tid / (BN / TN);   // 0..15
    int bm = blockIdx.y * BM;
    int bn = blockIdx.x * BN;

    float acc[TM][TN];
#pragma unroll
    for (int i = 0; i < TM; i++)
#pragma unroll
        for (int j = 0; j < TN; j++) acc[i][j] = 0.f;

    for (int k0 = 0; k0 < K; k0 += BK) {
        // Load A tile (128x8): 1024 elems / 256 threads = 4 each
#pragma unroll
        for (int i = 0; i < (BM * BK) / 256; i++) {
            int lin = tid + i * 256;
            int r = lin / BK, c = lin % BK;
            As[r][c] = A[(size_t)(bm + r) * K + k0 + c];
        }
        // Load B tile (8x128): fully coalesced
#pragma unroll
        for (int i = 0; i < (BK * BN) / 256; i++) {
            int lin = tid + i * 256;
            int r = lin / BN, c = lin % BN;
            Bs[r][c] = Bm[(size_t)(k0 + r) * N + bn + c];
        }
        __syncthreads();

#pragma unroll
        for (int k = 0; k < BK; k++) {
            float ra[TM], rb[TN];
#pragma unroll
            for (int i = 0; i < TM; i++) ra[i] = As[ty * TM + i][k];
#pragma unroll
            for (int j = 0; j < TN; j++) rb[j] = Bs[k][tx * TN + j];
#pragma unroll
            for (int i = 0; i < TM; i++)
#pragma unroll
                for (int j = 0; j < TN; j++) acc[i][j] = fmaf(ra[i], rb[j], acc[i][j]);
        }
        __syncthreads();
    }

#pragma unroll
    for (int i = 0; i < TM; i++) {
        int row = bm + ty * TM + i;
#pragma unroll
        for (int j = 0; j < TN; j++) {
            C[(size_t)row * N + bn + tx * TN + j] = acc[i][j];
        }
    }
}

// ---------------------------------------------------------------------------
// RoPE in-place: x is [B*S, nheads, HD]. One thread per rotation pair.
// cos/sin are [S, HD] with cos[s][d] == cos[s][d+32].
// ---------------------------------------------------------------------------
__global__ void rope_kernel(float* __restrict__ x, const float* __restrict__ cosT,
                            const float* __restrict__ sinT, int nheads, int total_pairs) {
    int idx = blockIdx.x * blockDim.x + threadIdx.x;
    if (idx >= total_pairs) return;
    int d = idx & 31;
    int h = (idx >> 5) % nheads;
    int row = idx / (32 * nheads);     // b*S + s
    int s = row % S_;
    float c  = cosT[s * HD_ + d];
    float sn = sinT[s * HD_ + d];
    float* p = x + ((size_t)row * nheads + h) * HD_;
    float x0 = p[d], x1 = p[d + 32];
    p[d]      = x0 * c - x1 * sn;
    p[d + 32] = x1 * c + x0 * sn;
}

// ---------------------------------------------------------------------------
// Flash attention (causal, GQA). Warp-per-query-row, 8 rows per block.
// grid = (B*HQ, S/8), block = 256.
// K tile padded (65) for conflict-free strided reads; V read as float2.
// ---------------------------------------------------------------------------
__global__ void flash_kernel(const float* __restrict__ q, const float* __restrict__ k,
                             const float* __restrict__ v, float* __restrict__ out) {
    __shared__ float Qs[8 * 64];
    __shared__ float Ks[64 * 65];
    __shared__ float Vs[64 * 64];

    int bh = blockIdx.x;
    int b = bh / HQ_, h = bh % HQ_;
    int kvh = h / (HQ_ / HKV_);
    int w = threadIdx.x >> 5, lane = threadIdx.x & 31;
    int qrow = blockIdx.y * 8 + w;

    // Load 8 query rows
    for (int i = threadIdx.x; i < 8 * 64; i += 256) {
        int r = i >> 6, d = i & 63;
        Qs[i] = q[(((size_t)(b * S_ + blockIdx.y * 8 + r)) * HQ_ + h) * HD_ + d];
    }

    float m = -1e30f, l = 0.f, o0 = 0.f, o1 = 0.f;
    int ntiles = (blockIdx.y * 8 + 7) / 64 + 1;

    for (int t = 0; t < ntiles; t++) {
        __syncthreads();
        for (int i = threadIdx.x; i < 64 * 64; i += 256) {
            int r = i >> 6, d = i & 63;
            int key = t * 64 + r;
            size_t gi = (((size_t)(b * S_ + key)) * HKV_ + kvh) * HD_ + d;
            Ks[r * 65 + d] = k[gi];
            Vs[i] = v[gi];
        }
        __syncthreads();

#pragma unroll
        for (int c = 0; c < 2; c++) {
            int key = t * 64 + c * 32 + lane;
            float s = 0.f;
            const float* qr = &Qs[w * 64];
            const float* kr = &Ks[(c * 32 + lane) * 65];
#pragma unroll
            for (int d = 0; d < 64; d++) s = fmaf(qr[d], kr[d], s);
            s *= 0.125f;                      // HD^-0.5
            if (key > qrow) s = -1e30f;       // causal mask (matches reference)

            float cm = s;
#pragma unroll
            for (int off = 16; off; off >>= 1)
                cm = fmaxf(cm, __shfl_xor_sync(0xFFFFFFFFu, cm, off));
            float mn = fmaxf(m, cm);
            float corr = __expf(m - mn);
            float p = __expf(s - mn);
            float ps = p;
#pragma unroll
            for (int off = 16; off; off >>= 1)
                ps += __shfl_xor_sync(0xFFFFFFFFu, ps, off);
            l = l * corr + ps;
            o0 *= corr; o1 *= corr;
#pragma unroll
            for (int j = 0; j < 32; j++) {
                float pj = __shfl_sync(0xFFFFFFFFu, p, j);
                float2 vv = *(const float2*)&Vs[(c * 32 + j) * 64 + 2 * lane];
                o0 = fmaf(pj, vv.x, o0);
                o1 = fmaf(pj, vv.y, o1);
            }
            m = mn;
        }
    }

    float inv = 1.f / l;
    size_t oi = (((size_t)(b * S_ + qrow)) * HQ_ + h) * HD_ + 2 * lane;
    out[oi]     = o0 * inv;
    out[oi + 1] = o1 * inv;
}

// ---------------------------------------------------------------------------
extern "C" void kernel_launch(void* const* d_in, const int* in_sizes, int n_in,
                              void* d_out, int out_size) {
    const float* hs   = (const float*)d_in[0];
    const float* cosT = (const float*)d_in[1];
    const float* sinT = (const float*)d_in[2];
    const float* Wq   = (const float*)d_in[3];
    const float* Wk   = (const float*)d_in[4];
    const float* Wv   = (const float*)d_in[5];
    const float* Wo   = (const float*)d_in[6];
    float* out = (float*)d_out;

    float *q, *k, *v, *att;
    cudaGetSymbolAddress((void**)&q,   g_q);
    cudaGetSymbolAddress((void**)&k,   g_k);
    cudaGetSymbolAddress((void**)&v,   g_v);
    cudaGetSymbolAddress((void**)&att, g_att);

    dim3 blk(256);
    // Projections
    sgemm128<<<dim3(HID_ / 128, M_ / 128), blk>>>(hs, Wq, q, M_, HID_, HID_);
    sgemm128<<<dim3(KV_  / 128, M_ / 128), blk>>>(hs, Wk, k, M_, KV_,  HID_);
    sgemm128<<<dim3(KV_  / 128, M_ / 128), blk>>>(hs, Wv, v, M_, KV_,  HID_);

    // RoPE
    int qpairs = M_ * HQ_ * 32;
    int kpairs = M_ * HKV_ * 32;
    rope_kernel<<<(qpairs + 255) / 256, blk>>>(q, cosT, sinT, HQ_, qpairs);
    rope_kernel<<<(kpairs + 255) / 256, blk>>>(k, cosT, sinT, HKV_, kpairs);

    // Attention
    flash_kernel<<<dim3(B_ * HQ_, S_ / 8), blk>>>(q, k, v, att);

    // Output projection
    sgemm128<<<dim3(HID_ / 128, M_ / 128), blk>>>(att, Wo, out, M_, HID_, HID_);
}

// round 4
// speedup vs baseline: 1.9712x; 1.9712x over previous
#include <cuda_runtime.h>
#include <cuda_bf16.h>
#include <cstdint>

// Problem dims
#define B_   2
#define S_   1024
#define HID_ 2048
#define HQ_  32
#define HKV_ 8
#define HD_  64
#define KV_  (HKV_*HD_)   // 512
#define M_   (B_*S_)      // 2048

// Scratch (device globals — no allocation allowed)
__device__ float g_q[M_*HID_];     // 16 MB
__device__ float g_k[M_*KV_];      //  4 MB
__device__ float g_v[M_*KV_];      //  4 MB
__device__ float g_att[M_*HID_];   // 16 MB

// ---------------------------------------------------------------------------
// TF32 tensor-core GEMM: C[MxN] = A[MxK] @ B[KxN], fp32 in/out.
// 128x128x32 CTA tile, 256 threads = 8 warps in 2(M) x 4(N), warp = 64x32.
// mma.sync.aligned.m16n8k8.row.col.f32.tf32.tf32.f32
// ---------------------------------------------------------------------------
__device__ __forceinline__ uint32_t f2tf32(float x) {
    uint32_t r;
    asm("cvt.rna.tf32.f32 %0, %1;" : "=r"(r) : "f"(x));
    return r;
}

__device__ __forceinline__ void mma_tf32(float* c, uint32_t a0, uint32_t a1,
                                         uint32_t a2, uint32_t a3,
                                         uint32_t b0, uint32_t b1) {
    asm volatile(
        "mma.sync.aligned.m16n8k8.row.col.f32.tf32.tf32.f32 "
        "{%0,%1,%2,%3}, {%4,%5,%6,%7}, {%8,%9}, {%0,%1,%2,%3};"
        : "+f"(c[0]), "+f"(c[1]), "+f"(c[2]), "+f"(c[3])
        : "r"(a0), "r"(a1), "r"(a2), "r"(a3), "r"(b0), "r"(b1));
}

#define BM 128
#define BN 128
#define BK 32
#define ASTRIDE 36    // BK+4: conflict-free for frag gather (bank = 4g+t, distinct)
#define BSTRIDE 136   // BN+8: conflict-free for frag gather (bank = 8t+n, distinct)

__global__ __launch_bounds__(256, 2)
void tgemm(const float* __restrict__ A, const float* __restrict__ Bm,
           float* __restrict__ C, int M, int N, int K) {
    __shared__ float As[BM][ASTRIDE];   // [m][k]
    __shared__ float Bs[BK][BSTRIDE];   // [k][n]

    const int tid  = threadIdx.x;
    const int warp = tid >> 5;
    const int lane = tid & 31;
    const int g = lane >> 2;      // group (8)
    const int t = lane & 3;       // thread-in-quad (4)
    const int wm = (warp & 1) * 64;
    const int wn = (warp >> 1) * 32;
    const int bm = blockIdx.y * BM;
    const int bn = blockIdx.x * BN;

    // A loader: row = tid>>3 (+32*i), col4 = (tid&7)*4
    const int a_r = tid >> 3;
    const int a_c = (tid & 7) * 4;
    // B loader: row = tid>>5 (+8*i), col4 = (tid&31)*4
    const int b_r = tid >> 5;
    const int b_c = (lane) * 4;

    float acc[4][4][4];
#pragma unroll
    for (int mi = 0; mi < 4; mi++)
#pragma unroll
        for (int ni = 0; ni < 4; ni++)
#pragma unroll
            for (int f = 0; f < 4; f++) acc[mi][ni][f] = 0.f;

    for (int k0 = 0; k0 < K; k0 += BK) {
        // Load A tile (128x32), transposing nothing: As[m][k], tf32-rounded
#pragma unroll
        for (int i = 0; i < 4; i++) {
            int r = a_r + 32 * i;
            float4 va = *(const float4*)&A[(size_t)(bm + r) * K + k0 + a_c];
            As[r][a_c + 0] = __uint_as_float(f2tf32(va.x));
            As[r][a_c + 1] = __uint_as_float(f2tf32(va.y));
            As[r][a_c + 2] = __uint_as_float(f2tf32(va.z));
            As[r][a_c + 3] = __uint_as_float(f2tf32(va.w));
        }
        // Load B tile (32x128): Bs[k][n], tf32-rounded
#pragma unroll
        for (int i = 0; i < 4; i++) {
            int r = b_r + 8 * i;
            float4 vb = *(const float4*)&Bm[(size_t)(k0 + r) * N + bn + b_c];
            Bs[r][b_c + 0] = __uint_as_float(f2tf32(vb.x));
            Bs[r][b_c + 1] = __uint_as_float(f2tf32(vb.y));
            Bs[r][b_c + 2] = __uint_as_float(f2tf32(vb.z));
            Bs[r][b_c + 3] = __uint_as_float(f2tf32(vb.w));
        }
        __syncthreads();

#pragma unroll
        for (int kk = 0; kk < BK; kk += 8) {
            // B fragments (shared across mi)
            uint32_t bf[4][2];
#pragma unroll
            for (int ni = 0; ni < 4; ni++) {
                int n = wn + 8 * ni + g;
                bf[ni][0] = __float_as_uint(Bs[kk + t][n]);
                bf[ni][1] = __float_as_uint(Bs[kk + t + 4][n]);
            }
#pragma unroll
            for (int mi = 0; mi < 4; mi++) {
                int m = wm + 16 * mi + g;
                uint32_t a0 = __float_as_uint(As[m][kk + t]);
                uint32_t a1 = __float_as_uint(As[m + 8][kk + t]);
                uint32_t a2 = __float_as_uint(As[m][kk + t + 4]);
                uint32_t a3 = __float_as_uint(As[m + 8][kk + t + 4]);
#pragma unroll
                for (int ni = 0; ni < 4; ni++)
                    mma_tf32(acc[mi][ni], a0, a1, a2, a3, bf[ni][0], bf[ni][1]);
            }
        }
        __syncthreads();
    }

    // Writeback: c0=C[g][2t], c1=C[g][2t+1], c2=C[g+8][2t], c3=C[g+8][2t+1]
#pragma unroll
    for (int mi = 0; mi < 4; mi++) {
#pragma unroll
        for (int ni = 0; ni < 4; ni++) {
            int r0 = bm + wm + 16 * mi + g;
            int col = bn + wn + 8 * ni + 2 * t;
            float2 v0 = make_float2(acc[mi][ni][0], acc[mi][ni][1]);
            float2 v1 = make_float2(acc[mi][ni][2], acc[mi][ni][3]);
            *(float2*)&C[(size_t)r0 * N + col] = v0;
            *(float2*)&C[(size_t)(r0 + 8) * N + col] = v1;
        }
    }
}

// ---------------------------------------------------------------------------
// RoPE in-place: x is [B*S, nheads, HD]. One thread per rotation pair.
// ---------------------------------------------------------------------------
__global__ void rope_kernel(float* __restrict__ x, const float* __restrict__ cosT,
                            const float* __restrict__ sinT, int nheads, int total_pairs) {
    int idx = blockIdx.x * blockDim.x + threadIdx.x;
    if (idx >= total_pairs) return;
    int d = idx & 31;
    int h = (idx >> 5) % nheads;
    int row = idx / (32 * nheads);     // b*S + s
    int s = row % S_;
    float c  = cosT[s * HD_ + d];
    float sn = sinT[s * HD_ + d];
    float* p = x + ((size_t)row * nheads + h) * HD_;
    float x0 = p[d], x1 = p[d + 32];
    p[d]      = x0 * c - x1 * sn;
    p[d + 32] = x1 * c + x0 * sn;
}

// ---------------------------------------------------------------------------
// Flash attention (causal, GQA). Warp-per-query-row, 8 rows per block.
// ---------------------------------------------------------------------------
__global__ void flash_kernel(const float* __restrict__ q, const float* __restrict__ k,
                             const float* __restrict__ v, float* __restrict__ out) {
    __shared__ float Qs[8 * 64];
    __shared__ float Ks[64 * 65];
    __shared__ float Vs[64 * 64];

    int bh = blockIdx.x;
    int b = bh / HQ_, h = bh % HQ_;
    int kvh = h / (HQ_ / HKV_);
    int w = threadIdx.x >> 5, lane = threadIdx.x & 31;
    int qrow = blockIdx.y * 8 + w;

    for (int i = threadIdx.x; i < 8 * 64; i += 256) {
        int r = i >> 6, d = i & 63;
        Qs[i] = q[(((size_t)(b * S_ + blockIdx.y * 8 + r)) * HQ_ + h) * HD_ + d];
    }

    float m = -1e30f, l = 0.f, o0 = 0.f, o1 = 0.f;
    int ntiles = (blockIdx.y * 8 + 7) / 64 + 1;

    for (int t = 0; t < ntiles; t++) {
        __syncthreads();
        for (int i = threadIdx.x; i < 64 * 64; i += 256) {
            int r = i >> 6, d = i & 63;
            int key = t * 64 + r;
            size_t gi = (((size_t)(b * S_ + key)) * HKV_ + kvh) * HD_ + d;
            Ks[r * 65 + d] = k[gi];
            Vs[i] = v[gi];
        }
        __syncthreads();

#pragma unroll
        for (int c = 0; c < 2; c++) {
            int key = t * 64 + c * 32 + lane;
            float s = 0.f;
            const float* qr = &Qs[w * 64];
            const float* kr = &Ks[(c * 32 + lane) * 65];
#pragma unroll
            for (int d = 0; d < 64; d++) s = fmaf(qr[d], kr[d], s);
            s *= 0.125f;
            if (key > qrow) s = -1e30f;

            float cm = s;
#pragma unroll
            for (int off = 16; off; off >>= 1)
                cm = fmaxf(cm, __shfl_xor_sync(0xFFFFFFFFu, cm, off));
            float mn = fmaxf(m, cm);
            float corr = __expf(m - mn);
            float p = __expf(s - mn);
            float ps = p;
#pragma unroll
            for (int off = 16; off; off >>= 1)
                ps += __shfl_xor_sync(0xFFFFFFFFu, ps, off);
            l = l * corr + ps;
            o0 *= corr; o1 *= corr;
#pragma unroll
            for (int j = 0; j < 32; j++) {
                float pj = __shfl_sync(0xFFFFFFFFu, p, j);
                float2 vv = *(const float2*)&Vs[(c * 32 + j) * 64 + 2 * lane];
                o0 = fmaf(pj, vv.x, o0);
                o1 = fmaf(pj, vv.y, o1);
            }
            m = mn;
        }
    }

    float inv = 1.f / l;
    size_t oi = (((size_t)(b * S_ + qrow)) * HQ_ + h) * HD_ + 2 * lane;
    out[oi]     = o0 * inv;
    out[oi + 1] = o1 * inv;
}

// ---------------------------------------------------------------------------
extern "C" void kernel_launch(void* const* d_in, const int* in_sizes, int n_in,
                              void* d_out, int out_size) {
    const float* hs   = (const float*)d_in[0];
    const float* cosT = (const float*)d_in[1];
    const float* sinT = (const float*)d_in[2];
    const float* Wq   = (const float*)d_in[3];
    const float* Wk   = (const float*)d_in[4];
    const float* Wv   = (const float*)d_in[5];
    const float* Wo   = (const float*)d_in[6];
    float* out = (float*)d_out;

    float *q, *k, *v, *att;
    cudaGetSymbolAddress((void**)&q,   g_q);
    cudaGetSymbolAddress((void**)&k,   g_k);
    cudaGetSymbolAddress((void**)&v,   g_v);
    cudaGetSymbolAddress((void**)&att, g_att);

    dim3 blk(256);
    // Projections (TF32 tensor cores)
    tgemm<<<dim3(HID_ / BN, M_ / BM), blk>>>(hs, Wq, q, M_, HID_, HID_);
    tgemm<<<dim3(KV_  / BN, M_ / BM), blk>>>(hs, Wk, k, M_, KV_,  HID_);
    tgemm<<<dim3(KV_  / BN, M_ / BM), blk>>>(hs, Wv, v, M_, KV_,  HID_);

    // RoPE
    int qpairs = M_ * HQ_ * 32;
    int kpairs = M_ * HKV_ * 32;
    rope_kernel<<<(qpairs + 255) / 256, blk>>>(q, cosT, sinT, HQ_, qpairs);
    rope_kernel<<<(kpairs + 255) / 256, blk>>>(k, cosT, sinT, HKV_, kpairs);

    // Attention
    flash_kernel<<<dim3(B_ * HQ_, S_ / 8), blk>>>(q, k, v, att);

    // Output projection
    tgemm<<<dim3(HID_ / BN, M_ / BM), blk>>>(att, Wo, out, M_, HID_, HID_);
}

// round 7
// speedup vs baseline: 2.3764x; 1.2056x over previous
#include <cuda_runtime.h>
#include <cuda_bf16.h>
#include <cstdint>

// Problem dims
#define B_   2
#define S_   1024
#define HID_ 2048
#define HQ_  32
#define HKV_ 8
#define HD_  64
#define KV_  (HKV_*HD_)   // 512
#define M_   (B_*S_)      // 2048

// Scratch (device globals — no allocation allowed)
__device__ float g_q[M_*HID_];     // 16 MB
__device__ float g_k[M_*KV_];      //  4 MB
__device__ float g_v[M_*KV_];      //  4 MB
__device__ float g_att[M_*HID_];   // 16 MB

// ---------------------------------------------------------------------------
// TF32 tensor-core GEMM, cp.async double-buffered, static SMEM (37.9 KB).
// C[MxN] = A[MxK] @ B[KxN], fp32 in/out.
// 128x128x16 CTA tile, 256 threads = 8 warps in 2(M) x 4(N), warp = 64x32.
// ---------------------------------------------------------------------------
__device__ __forceinline__ uint32_t f2tf32(float x) {
    uint32_t r;
    asm("cvt.rna.tf32.f32 %0, %1;" : "=r"(r) : "f"(x));
    return r;
}

__device__ __forceinline__ void mma_tf32(float* c, uint32_t a0, uint32_t a1,
                                         uint32_t a2, uint32_t a3,
                                         uint32_t b0, uint32_t b1) {
    asm volatile(
        "mma.sync.aligned.m16n8k8.row.col.f32.tf32.tf32.f32 "
        "{%0,%1,%2,%3}, {%4,%5,%6,%7}, {%8,%9}, {%0,%1,%2,%3};"
        : "+f"(c[0]), "+f"(c[1]), "+f"(c[2]), "+f"(c[3])
        : "r"(a0), "r"(a1), "r"(a2), "r"(a3), "r"(b0), "r"(b1));
}

__device__ __forceinline__ void cp16(void* smem, const void* g) {
    uint32_t s = (uint32_t)__cvta_generic_to_shared(smem);
    asm volatile("cp.async.cg.shared.global [%0], [%1], 16;" :: "r"(s), "l"(g));
}

#define BM 128
#define BN 128
#define BK 16
#define ASTRIDE 20    // BK+4: frag gather bank = (20g+t)%32 -> all 32 distinct
#define BSTRIDE 136   // BN+8: frag gather bank = (8t+g)%32  -> all 32 distinct

__device__ __forceinline__ void tgemm_core(const float* __restrict__ A,
                                           const float* __restrict__ Bm,
                                           float* __restrict__ C,
                                           int N, int K) {
    __shared__ float As[2][BM][ASTRIDE];   // 2*128*20*4  = 20480 B
    __shared__ float Bs[2][BK][BSTRIDE];   // 2*16*136*4  = 17408 B

    const int tid  = threadIdx.x;
    const int warp = tid >> 5;
    const int lane = tid & 31;
    const int g = lane >> 2;
    const int t = lane & 3;
    const int wm = (warp & 1) * 64;
    const int wn = (warp >> 1) * 32;
    const int bm = blockIdx.y * BM;
    const int bn = blockIdx.x * BN;

    // A loader: 128x16 = 2048 floats, 256 threads * 2 float4
    const int a_r = tid >> 2;          // 0..63, +64
    const int a_c = (tid & 3) * 4;
    // B loader: 16x128 = 2048 floats, 256 threads * 2 float4
    const int b_r = tid >> 5;          // 0..7, +8
    const int b_c = lane * 4;

    float acc[4][4][4];
#pragma unroll
    for (int mi = 0; mi < 4; mi++)
#pragma unroll
        for (int ni = 0; ni < 4; ni++)
#pragma unroll
            for (int f = 0; f < 4; f++) acc[mi][ni][f] = 0.f;

#define ISSUE_TILE(buf, k0)                                                   \
    {                                                                         \
        _Pragma("unroll")                                                     \
        for (int i = 0; i < 2; i++) {                                         \
            int r = a_r + 64 * i;                                             \
            cp16(&As[buf][r][a_c], &A[(size_t)(bm + r) * K + (k0) + a_c]);    \
        }                                                                     \
        _Pragma("unroll")                                                     \
        for (int i = 0; i < 2; i++) {                                         \
            int r = b_r + 8 * i;                                              \
            cp16(&Bs[buf][r][b_c], &Bm[(size_t)((k0) + r) * N + bn + b_c]);   \
        }                                                                     \
        asm volatile("cp.async.commit_group;");                               \
    }

    const int NIT = K / BK;
    ISSUE_TILE(0, 0);

    for (int it = 0; it < NIT; it++) {
        const int cur = it & 1;
        if (it + 1 < NIT) {
            ISSUE_TILE(cur ^ 1, (it + 1) * BK);
            asm volatile("cp.async.wait_group 1;");
        } else {
            asm volatile("cp.async.wait_group 0;");
        }
        __syncthreads();

#pragma unroll
        for (int kk = 0; kk < BK; kk += 8) {
            uint32_t bf[4][2];
#pragma unroll
            for (int ni = 0; ni < 4; ni++) {
                int n = wn + 8 * ni + g;
                bf[ni][0] = f2tf32(Bs[cur][kk + t][n]);
                bf[ni][1] = f2tf32(Bs[cur][kk + t + 4][n]);
            }
#pragma unroll
            for (int mi = 0; mi < 4; mi++) {
                int m = wm + 16 * mi + g;
                uint32_t a0 = f2tf32(As[cur][m][kk + t]);
                uint32_t a1 = f2tf32(As[cur][m + 8][kk + t]);
                uint32_t a2 = f2tf32(As[cur][m][kk + t + 4]);
                uint32_t a3 = f2tf32(As[cur][m + 8][kk + t + 4]);
#pragma unroll
                for (int ni = 0; ni < 4; ni++)
                    mma_tf32(acc[mi][ni], a0, a1, a2, a3, bf[ni][0], bf[ni][1]);
            }
        }
        __syncthreads();
    }
#undef ISSUE_TILE

#pragma unroll
    for (int mi = 0; mi < 4; mi++) {
#pragma unroll
        for (int ni = 0; ni < 4; ni++) {
            int r0 = bm + wm + 16 * mi + g;
            int col = bn + wn + 8 * ni + 2 * t;
            *(float2*)&C[(size_t)r0 * N + col] =
                make_float2(acc[mi][ni][0], acc[mi][ni][1]);
            *(float2*)&C[(size_t)(r0 + 8) * N + col] =
                make_float2(acc[mi][ni][2], acc[mi][ni][3]);
        }
    }
}

__global__ __launch_bounds__(256)
void tgemm_q(const float* __restrict__ A, const float* __restrict__ Bm,
             float* __restrict__ C, int N, int K) {
    tgemm_core(A, Bm, C, N, K);
}

// Merged K+V projection: blockIdx.z selects weight/output.
__global__ __launch_bounds__(256)
void tgemm_kv(const float* __restrict__ A,
              const float* __restrict__ Wk, const float* __restrict__ Wv,
              float* __restrict__ k, float* __restrict__ v, int N, int K) {
    const float* Bm = blockIdx.z ? Wv : Wk;
    float* C = blockIdx.z ? v : k;
    tgemm_core(A, Bm, C, N, K);
}

// ---------------------------------------------------------------------------
// RoPE in-place: x is [B*S, nheads, HD]. One thread per rotation pair.
// ---------------------------------------------------------------------------
__global__ void rope_kernel(float* __restrict__ x, const float* __restrict__ cosT,
                            const float* __restrict__ sinT, int nheads, int total_pairs) {
    int idx = blockIdx.x * blockDim.x + threadIdx.x;
    if (idx >= total_pairs) return;
    int d = idx & 31;
    int h = (idx >> 5) % nheads;
    int row = idx / (32 * nheads);     // b*S + s
    int s = row % S_;
    float c  = cosT[s * HD_ + d];
    float sn = sinT[s * HD_ + d];
    float* p = x + ((size_t)row * nheads + h) * HD_;
    float x0 = p[d], x1 = p[d + 32];
    p[d]      = x0 * c - x1 * sn;
    p[d + 32] = x1 * c + x0 * sn;
}

// ---------------------------------------------------------------------------
// Flash attention (causal, GQA). 2 query rows per warp, 16 rows per block.
// grid = (B*HQ, S/16), block = 256.
// ---------------------------------------------------------------------------
__global__ __launch_bounds__(256)
void flash_kernel(const float* __restrict__ q, const float* __restrict__ k,
                  const float* __restrict__ v, float* __restrict__ out) {
    __shared__ float Qs[16 * 64];
    __shared__ float Ks[64 * 65];
    __shared__ float Vs[64 * 64];

    int bh = blockIdx.x;
    int b = bh / HQ_, h = bh % HQ_;
    int kvh = h / (HQ_ / HKV_);
    int w = threadIdx.x >> 5, lane = threadIdx.x & 31;
    int rbase = blockIdx.y * 16;
    int qr0 = rbase + 2 * w;
    int qr1 = qr0 + 1;

    for (int i = threadIdx.x; i < 16 * 64; i += 256) {
        int r = i >> 6, d = i & 63;
        Qs[i] = q[(((size_t)(b * S_ + rbase + r)) * HQ_ + h) * HD_ + d];
    }

    float m0 = -1e30f, l0 = 0.f, o00 = 0.f, o01 = 0.f;
    float m1 = -1e30f, l1 = 0.f, o10 = 0.f, o11 = 0.f;
    int ntiles = (rbase + 15) / 64 + 1;

    for (int t = 0; t < ntiles; t++) {
        __syncthreads();
        for (int i = threadIdx.x; i < 64 * 64; i += 256) {
            int r = i >> 6, d = i & 63;
            size_t gi = (((size_t)(b * S_ + t * 64 + r)) * HKV_ + kvh) * HD_ + d;
            Ks[r * 65 + d] = k[gi];
            Vs[i] = v[gi];
        }
        __syncthreads();

#pragma unroll
        for (int c = 0; c < 2; c++) {
            int key = t * 64 + c * 32 + lane;
            const float* qra = &Qs[(2 * w) * 64];
            const float* qrb = qra + 64;
            const float* kr = &Ks[(c * 32 + lane) * 65];
            float s0 = 0.f, s1 = 0.f;
#pragma unroll
            for (int d = 0; d < 64; d++) {
                float kv = kr[d];
                s0 = fmaf(qra[d], kv, s0);
                s1 = fmaf(qrb[d], kv, s1);
            }
            s0 *= 0.125f; s1 *= 0.125f;
            if (key > qr0) s0 = -1e30f;
            if (key > qr1) s1 = -1e30f;

            float cm0 = s0, cm1 = s1;
#pragma unroll
            for (int off = 16; off; off >>= 1) {
                cm0 = fmaxf(cm0, __shfl_xor_sync(0xFFFFFFFFu, cm0, off));
                cm1 = fmaxf(cm1, __shfl_xor_sync(0xFFFFFFFFu, cm1, off));
            }
            float mn0 = fmaxf(m0, cm0), mn1 = fmaxf(m1, cm1);
            float corr0 = __expf(m0 - mn0), corr1 = __expf(m1 - mn1);
            float p0 = __expf(s0 - mn0), p1 = __expf(s1 - mn1);
            float ps0 = p0, ps1 = p1;
#pragma unroll
            for (int off = 16; off; off >>= 1) {
                ps0 += __shfl_xor_sync(0xFFFFFFFFu, ps0, off);
                ps1 += __shfl_xor_sync(0xFFFFFFFFu, ps1, off);
            }
            l0 = l0 * corr0 + ps0;
            l1 = l1 * corr1 + ps1;
            o00 *= corr0; o01 *= corr0;
            o10 *= corr1; o11 *= corr1;
#pragma unroll
            for (int j = 0; j < 32; j++) {
                float pj0 = __shfl_sync(0xFFFFFFFFu, p0, j);
                float pj1 = __shfl_sync(0xFFFFFFFFu, p1, j);
                float2 vv = *(const float2*)&Vs[(c * 32 + j) * 64 + 2 * lane];
                o00 = fmaf(pj0, vv.x, o00);
                o01 = fmaf(pj0, vv.y, o01);
                o10 = fmaf(pj1, vv.x, o10);
                o11 = fmaf(pj1, vv.y, o11);
            }
            m0 = mn0; m1 = mn1;
        }
    }

    float inv0 = 1.f / l0, inv1 = 1.f / l1;
    size_t oi0 = (((size_t)(b * S_ + qr0)) * HQ_ + h) * HD_ + 2 * lane;
    size_t oi1 = (((size_t)(b * S_ + qr1)) * HQ_ + h) * HD_ + 2 * lane;
    out[oi0]     = o00 * inv0;
    out[oi0 + 1] = o01 * inv0;
    out[oi1]     = o10 * inv1;
    out[oi1 + 1] = o11 * inv1;
}

// ---------------------------------------------------------------------------
extern "C" void kernel_launch(void* const* d_in, const int* in_sizes, int n_in,
                              void* d_out, int out_size) {
    const float* hs   = (const float*)d_in[0];
    const float* cosT = (const float*)d_in[1];
    const float* sinT = (const float*)d_in[2];
    const float* Wq   = (const float*)d_in[3];
    const float* Wk   = (const float*)d_in[4];
    const float* Wv   = (const float*)d_in[5];
    const float* Wo   = (const float*)d_in[6];
    float* out = (float*)d_out;

    float *q, *k, *v, *att;
    cudaGetSymbolAddress((void**)&q,   g_q);
    cudaGetSymbolAddress((void**)&k,   g_k);
    cudaGetSymbolAddress((void**)&v,   g_v);
    cudaGetSymbolAddress((void**)&att, g_att);

    dim3 blk(256);
    // Q projection (TF32 TC, cp.async pipelined)
    tgemm_q<<<dim3(HID_ / BN, M_ / BM), blk>>>(hs, Wq, q, HID_, HID_);
    // K + V projections merged (128 CTAs)
    tgemm_kv<<<dim3(KV_ / BN, M_ / BM, 2), blk>>>(hs, Wk, Wv, k, v, KV_, HID_);

    // RoPE
    int qpairs = M_ * HQ_ * 32;
    int kpairs = M_ * HKV_ * 32;
    rope_kernel<<<(qpairs + 255) / 256, blk>>>(q, cosT, sinT, HQ_, qpairs);
    rope_kernel<<<(kpairs + 255) / 256, blk>>>(k, cosT, sinT, HKV_, kpairs);

    // Attention (2 rows/warp)
    flash_kernel<<<dim3(B_ * HQ_, S_ / 16), blk>>>(q, k, v, att);

    // Output projection
    tgemm_q<<<dim3(HID_ / BN, M_ / BM), blk>>>(att, Wo, out, HID_, HID_);
}

// round 14
// speedup vs baseline: 5.0770x; 2.1364x over previous
#include <cuda_runtime.h>
#include <cuda_bf16.h>
#include <cstdint>

// Problem dims
#define B_   2
#define S_   1024
#define HID_ 2048
#define HQ_  32
#define HKV_ 8
#define HD_  64
#define KV_  (HKV_*HD_)   // 512
#define M_   (B_*S_)      // 2048

// Scratch (device globals — no allocation allowed)
__device__ float g_q[M_*HID_];     // 16 MB
__device__ float g_k[M_*KV_];      //  4 MB
__device__ float g_v[M_*KV_];      //  4 MB
__device__ float g_att[M_*HID_];   // 16 MB

// ---------------------------------------------------------------------------
// Common helpers
// ---------------------------------------------------------------------------
__device__ __forceinline__ uint32_t f2tf32(float x) {
    uint32_t r;
    asm("cvt.rna.tf32.f32 %0, %1;" : "=r"(r) : "f"(x));
    return r;
}

__device__ __forceinline__ void mma_tf32(float* c, uint32_t a0, uint32_t a1,
                                         uint32_t a2, uint32_t a3,
                                         uint32_t b0, uint32_t b1) {
    asm volatile(
        "mma.sync.aligned.m16n8k8.row.col.f32.tf32.tf32.f32 "
        "{%0,%1,%2,%3}, {%4,%5,%6,%7}, {%8,%9}, {%0,%1,%2,%3};"
        : "+f"(c[0]), "+f"(c[1]), "+f"(c[2]), "+f"(c[3])
        : "r"(a0), "r"(a1), "r"(a2), "r"(a3), "r"(b0), "r"(b1));
}

__device__ __forceinline__ void cp16(void* smem, const void* g) {
    uint32_t s = (uint32_t)__cvta_generic_to_shared(smem);
    asm volatile("cp.async.cg.shared.global [%0], [%1], 16;" :: "r"(s), "l"(g));
}

// ---------------------------------------------------------------------------
// TF32 GEMM: C[MxN] = A[MxK] @ B[KxN]. CTA 128x128x16, 128 threads = 4 warps,
// warp tile 64x64 (2Mx2N warps). cp.async double-buffered, static SMEM.
// ---------------------------------------------------------------------------
#define BM 128
#define BN 128
#define BK 16
#define ASTRIDE 20    // bank(20g+t)%32 all distinct
#define BSTRIDE 136   // bank(8t+g)%32 all distinct

__device__ __forceinline__ void tgemm_core(const float* __restrict__ A,
                                           const float* __restrict__ Bm,
                                           float* __restrict__ C,
                                           int N, int K) {
    __shared__ float As[2][BM][ASTRIDE];   // 20480 B
    __shared__ float Bs[2][BK][BSTRIDE];   // 17408 B

    const int tid  = threadIdx.x;
    const int warp = tid >> 5;
    const int lane = tid & 31;
    const int g = lane >> 2;
    const int t = lane & 3;
    const int wm = (warp & 1) * 64;
    const int wn = (warp >> 1) * 64;
    const int bm = blockIdx.y * BM;
    const int bn = blockIdx.x * BN;

    // Loaders (128 threads): A 128x16 = 512 f4, B 16x128 = 512 f4, 4 each
    const int a_r = tid >> 2;          // +32*i
    const int a_c = (tid & 3) * 4;
    const int b_r = tid >> 5;          // +4*i
    const int b_c = lane * 4;

    float acc[4][8][4];
#pragma unroll
    for (int mi = 0; mi < 4; mi++)
#pragma unroll
        for (int ni = 0; ni < 8; ni++)
#pragma unroll
            for (int f = 0; f < 4; f++) acc[mi][ni][f] = 0.f;

#define ISSUE_TILE(buf, k0)                                                   \
    {                                                                         \
        _Pragma("unroll")                                                     \
        for (int i = 0; i < 4; i++) {                                         \
            int r = a_r + 32 * i;                                             \
            cp16(&As[buf][r][a_c], &A[(size_t)(bm + r) * K + (k0) + a_c]);    \
        }                                                                     \
        _Pragma("unroll")                                                     \
        for (int i = 0; i < 4; i++) {                                         \
            int r = b_r + 4 * i;                                              \
            cp16(&Bs[buf][r][b_c], &Bm[(size_t)((k0) + r) * N + bn + b_c]);   \
        }                                                                     \
        asm volatile("cp.async.commit_group;");                               \
    }

    const int NIT = K / BK;
    ISSUE_TILE(0, 0);

    for (int it = 0; it < NIT; it++) {
        const int cur = it & 1;
        if (it + 1 < NIT) {
            ISSUE_TILE(cur ^ 1, (it + 1) * BK);
            asm volatile("cp.async.wait_group 1;");
        } else {
            asm volatile("cp.async.wait_group 0;");
        }
        __syncthreads();

#pragma unroll
        for (int kk = 0; kk < BK; kk += 8) {
            uint32_t bf[8][2];
#pragma unroll
            for (int ni = 0; ni < 8; ni++) {
                int n = wn + 8 * ni + g;
                bf[ni][0] = f2tf32(Bs[cur][kk + t][n]);
                bf[ni][1] = f2tf32(Bs[cur][kk + t + 4][n]);
            }
#pragma unroll
            for (int mi = 0; mi < 4; mi++) {
                int m = wm + 16 * mi + g;
                uint32_t a0 = f2tf32(As[cur][m][kk + t]);
                uint32_t a1 = f2tf32(As[cur][m + 8][kk + t]);
                uint32_t a2 = f2tf32(As[cur][m][kk + t + 4]);
                uint32_t a3 = f2tf32(As[cur][m + 8][kk + t + 4]);
#pragma unroll
                for (int ni = 0; ni < 8; ni++)
                    mma_tf32(acc[mi][ni], a0, a1, a2, a3, bf[ni][0], bf[ni][1]);
            }
        }
        __syncthreads();
    }
#undef ISSUE_TILE

#pragma unroll
    for (int mi = 0; mi < 4; mi++) {
#pragma unroll
        for (int ni = 0; ni < 8; ni++) {
            int r0 = bm + wm + 16 * mi + g;
            int col = bn + wn + 8 * ni + 2 * t;
            *(float2*)&C[(size_t)r0 * N + col] =
                make_float2(acc[mi][ni][0], acc[mi][ni][1]);
            *(float2*)&C[(size_t)(r0 + 8) * N + col] =
                make_float2(acc[mi][ni][2], acc[mi][ni][3]);
        }
    }
}

__global__ __launch_bounds__(128)
void tgemm_q(const float* __restrict__ A, const float* __restrict__ Bm,
             float* __restrict__ C, int N, int K) {
    tgemm_core(A, Bm, C, N, K);
}

__global__ __launch_bounds__(128)
void tgemm_kv(const float* __restrict__ A,
              const float* __restrict__ Wk, const float* __restrict__ Wv,
              float* __restrict__ k, float* __restrict__ v, int N, int K) {
    tgemm_core(A, blockIdx.z ? Wv : Wk, blockIdx.z ? v : k, N, K);
}

// ---------------------------------------------------------------------------
// RoPE in-place
// ---------------------------------------------------------------------------
__global__ void rope_kernel(float* __restrict__ x, const float* __restrict__ cosT,
                            const float* __restrict__ sinT, int nheads, int total_pairs) {
    int idx = blockIdx.x * blockDim.x + threadIdx.x;
    if (idx >= total_pairs) return;
    int d = idx & 31;
    int h = (idx >> 5) % nheads;
    int row = idx / (32 * nheads);
    int s = row % S_;
    float c  = cosT[s * HD_ + d];
    float sn = sinT[s * HD_ + d];
    float* p = x + ((size_t)row * nheads + h) * HD_;
    float x0 = p[d], x1 = p[d + 32];
    p[d]      = x0 * c - x1 * sn;
    p[d + 32] = x1 * c + x0 * sn;
}

// ---------------------------------------------------------------------------
// Flash attention on tensor cores (tf32 mma). CTA: 64 q rows, one (b,h),
// 128 threads = 4 warps (each m16). KV tiles of 32 keys.
// QK: A=Q frags (regs), B=KsT[d][key] (stride 40).  Softmax on fragments.
// P -> SMEM Ps (stride 36) -> A frags for PV. V natural Vs[key][d] (stride 72).
// ---------------------------------------------------------------------------
__global__ __launch_bounds__(128)
void flash_mma(const float* __restrict__ q, const float* __restrict__ k,
               const float* __restrict__ v, float* __restrict__ out) {
    __shared__ float KsT[64][40];   // [d][key]   10240 B
    __shared__ float Vs[32][72];    // [key][d]    9216 B
    __shared__ float Ps[64][36];    // [qrow][key] 9216 B

    const int bh = blockIdx.x;
    const int b = bh / HQ_, h = bh % HQ_;
    const int kvh = h / (HQ_ / HKV_);
    const int q0 = blockIdx.y * 64;
    const int w = threadIdx.x >> 5, lane = threadIdx.x & 31;
    const int g = lane >> 2, t = lane & 3;
    const int wm = w * 16;
    const int r0 = q0 + wm + g, r1 = r0 + 8;

    // Preload Q fragments (tf32) straight from global
    uint32_t qa[8][4];
#pragma unroll
    for (int ks = 0; ks < 8; ks++) {
        size_t ba0 = (((size_t)(b * S_ + r0)) * HQ_ + h) * HD_ + 8 * ks;
        size_t ba1 = (((size_t)(b * S_ + r1)) * HQ_ + h) * HD_ + 8 * ks;
        qa[ks][0] = f2tf32(q[ba0 + t]);
        qa[ks][1] = f2tf32(q[ba1 + t]);
        qa[ks][2] = f2tf32(q[ba0 + t + 4]);
        qa[ks][3] = f2tf32(q[ba1 + t + 4]);
    }

    float m0 = -1e30f, m1 = -1e30f, l0 = 0.f, l1 = 0.f;
    float o[8][4];
#pragma unroll
    for (int ni = 0; ni < 8; ni++)
#pragma unroll
        for (int f = 0; f < 4; f++) o[ni][f] = 0.f;

    const int ntiles = q0 / 32 + 2;
    for (int tl = 0; tl < ntiles; tl++) {
        const int key0 = tl * 32;
        __syncthreads();
        // Fill KsT (transposed) and Vs (natural), tf32-rounded
#pragma unroll
        for (int i = threadIdx.x; i < 512; i += 128) {
            int key = i >> 4, d4 = (i & 15) * 4;
            size_t gi = (((size_t)(b * S_ + key0 + key)) * HKV_ + kvh) * HD_ + d4;
            float4 kv = *(const float4*)&k[gi];
            KsT[d4 + 0][key] = __uint_as_float(f2tf32(kv.x));
            KsT[d4 + 1][key] = __uint_as_float(f2tf32(kv.y));
            KsT[d4 + 2][key] = __uint_as_float(f2tf32(kv.z));
            KsT[d4 + 3][key] = __uint_as_float(f2tf32(kv.w));
            float4 vv = *(const float4*)&v[gi];
            float4 vc;
            vc.x = __uint_as_float(f2tf32(vv.x));
            vc.y = __uint_as_float(f2tf32(vv.y));
            vc.z = __uint_as_float(f2tf32(vv.z));
            vc.w = __uint_as_float(f2tf32(vv.w));
            *(float4*)&Vs[key][d4] = vc;
        }
        __syncthreads();

        // ---- QK^T: 16 rows x 32 keys per warp ----
        float s[4][4];
#pragma unroll
        for (int ni = 0; ni < 4; ni++)
#pragma unroll
            for (int f = 0; f < 4; f++) s[ni][f] = 0.f;
#pragma unroll
        for (int ks = 0; ks < 8; ks++) {
#pragma unroll
            for (int ni = 0; ni < 4; ni++) {
                uint32_t b0 = __float_as_uint(KsT[8 * ks + t][8 * ni + g]);
                uint32_t b1 = __float_as_uint(KsT[8 * ks + t + 4][8 * ni + g]);
                mma_tf32(s[ni], qa[ks][0], qa[ks][1], qa[ks][2], qa[ks][3], b0, b1);
            }
        }

        // ---- scale + causal mask + online softmax on fragments ----
        float rm0 = -1e30f, rm1 = -1e30f;
#pragma unroll
        for (int ni = 0; ni < 4; ni++) {
            int c0 = key0 + 8 * ni + 2 * t, c1 = c0 + 1;
            s[ni][0] = (c0 > r0) ? -1e30f : s[ni][0] * 0.125f;
            s[ni][1] = (c1 > r0) ? -1e30f : s[ni][1] * 0.125f;
            s[ni][2] = (c0 > r1) ? -1e30f : s[ni][2] * 0.125f;
            s[ni][3] = (c1 > r1) ? -1e30f : s[ni][3] * 0.125f;
            rm0 = fmaxf(rm0, fmaxf(s[ni][0], s[ni][1]));
            rm1 = fmaxf(rm1, fmaxf(s[ni][2], s[ni][3]));
        }
#pragma unroll
        for (int off = 1; off <= 2; off <<= 1) {
            rm0 = fmaxf(rm0, __shfl_xor_sync(0xFFFFFFFFu, rm0, off));
            rm1 = fmaxf(rm1, __shfl_xor_sync(0xFFFFFFFFu, rm1, off));
        }
        float mn0 = fmaxf(m0, rm0), mn1 = fmaxf(m1, rm1);
        float corr0 = __expf(m0 - mn0), corr1 = __expf(m1 - mn1);
        float p[4][4];
        float ps0 = 0.f, ps1 = 0.f;
#pragma unroll
        for (int ni = 0; ni < 4; ni++) {
            p[ni][0] = __expf(s[ni][0] - mn0);
            p[ni][1] = __expf(s[ni][1] - mn0);
            p[ni][2] = __expf(s[ni][2] - mn1);
            p[ni][3] = __expf(s[ni][3] - mn1);
            ps0 += p[ni][0] + p[ni][1];
            ps1 += p[ni][2] + p[ni][3];
        }
#pragma unroll
        for (int off = 1; off <= 2; off <<= 1) {
            ps0 += __shfl_xor_sync(0xFFFFFFFFu, ps0, off);
            ps1 += __shfl_xor_sync(0xFFFFFFFFu, ps1, off);
        }
        l0 = l0 * corr0 + ps0;
        l1 = l1 * corr1 + ps1;
#pragma unroll
        for (int ni = 0; ni < 8; ni++) {
            o[ni][0] *= corr0; o[ni][1] *= corr0;
            o[ni][2] *= corr1; o[ni][3] *= corr1;
        }
        // Store P (tf32) to own warp's rows
#pragma unroll
        for (int ni = 0; ni < 4; ni++) {
            *(float2*)&Ps[wm + g][8 * ni + 2 * t] = make_float2(
                __uint_as_float(f2tf32(p[ni][0])), __uint_as_float(f2tf32(p[ni][1])));
            *(float2*)&Ps[wm + g + 8][8 * ni + 2 * t] = make_float2(
                __uint_as_float(f2tf32(p[ni][2])), __uint_as_float(f2tf32(p[ni][3])));
        }
        __syncwarp();

        // ---- P @ V: 16 rows x 64 d per warp ----
#pragma unroll
        for (int ks = 0; ks < 4; ks++) {
            uint32_t a0 = __float_as_uint(Ps[wm + g][8 * ks + t]);
            uint32_t a1 = __float_as_uint(Ps[wm + g + 8][8 * ks + t]);
            uint32_t a2 = __float_as_uint(Ps[wm + g][8 * ks + t + 4]);
            uint32_t a3 = __float_as_uint(Ps[wm + g + 8][8 * ks + t + 4]);
#pragma unroll
            for (int ni = 0; ni < 8; ni++) {
                uint32_t b0 = __float_as_uint(Vs[8 * ks + t][8 * ni + g]);
                uint32_t b1 = __float_as_uint(Vs[8 * ks + t + 4][8 * ni + g]);
                mma_tf32(o[ni], a0, a1, a2, a3, b0, b1);
            }
        }
        m0 = mn0; m1 = mn1;
    }

    float inv0 = 1.f / l0, inv1 = 1.f / l1;
#pragma unroll
    for (int ni = 0; ni < 8; ni++) {
        int col = 8 * ni + 2 * t;
        *(float2*)&out[(((size_t)(b * S_ + r0)) * HQ_ + h) * HD_ + col] =
            make_float2(o[ni][0] * inv0, o[ni][1] * inv0);
        *(float2*)&out[(((size_t)(b * S_ + r1)) * HQ_ + h) * HD_ + col] =
            make_float2(o[ni][2] * inv1, o[ni][3] * inv1);
    }
}

// ---------------------------------------------------------------------------
extern "C" void kernel_launch(void* const* d_in, const int* in_sizes, int n_in,
                              void* d_out, int out_size) {
    const float* hs   = (const float*)d_in[0];
    const float* cosT = (const float*)d_in[1];
    const float* sinT = (const float*)d_in[2];
    const float* Wq   = (const float*)d_in[3];
    const float* Wk   = (const float*)d_in[4];
    const float* Wv   = (const float*)d_in[5];
    const float* Wo   = (const float*)d_in[6];
    float* out = (float*)d_out;

    float *q, *k, *v, *att;
    cudaGetSymbolAddress((void**)&q,   g_q);
    cudaGetSymbolAddress((void**)&k,   g_k);
    cudaGetSymbolAddress((void**)&v,   g_v);
    cudaGetSymbolAddress((void**)&att, g_att);

    dim3 blk(128);
    // Projections (TF32 TC, 64x64 warp tiles)
    tgemm_q<<<dim3(HID_ / BN, M_ / BM), blk>>>(hs, Wq, q, HID_, HID_);
    tgemm_kv<<<dim3(KV_ / BN, M_ / BM, 2), blk>>>(hs, Wk, Wv, k, v, KV_, HID_);

    // RoPE
    int qpairs = M_ * HQ_ * 32;
    int kpairs = M_ * HKV_ * 32;
    rope_kernel<<<(qpairs + 255) / 256, 256>>>(q, cosT, sinT, HQ_, qpairs);
    rope_kernel<<<(kpairs + 255) / 256, 256>>>(k, cosT, sinT, HKV_, kpairs);

    // Attention (tensor-core flash)
    flash_mma<<<dim3(B_ * HQ_, S_ / 64), blk>>>(q, k, v, att);

    // Output projection
    tgemm_q<<<dim3(HID_ / BN, M_ / BM), blk>>>(att, Wo, out, HID_, HID_);
}

// round 15
// speedup vs baseline: 5.1147x; 1.0074x over previous
#include <cuda_runtime.h>
#include <cuda_bf16.h>
#include <cstdint>

// Problem dims
#define B_   2
#define S_   1024
#define HID_ 2048
#define HQ_  32
#define HKV_ 8
#define HD_  64
#define KV_  (HKV_*HD_)   // 512
#define M_   (B_*S_)      // 2048

// Scratch (device globals — no allocation allowed)
__device__ float g_q[M_*HID_];      // 16 MB
__device__ float g_k[M_*KV_];       //  4 MB
__device__ float g_v[M_*KV_];       //  4 MB
__device__ float g_att[M_*HID_];    // 16 MB
// tf32-prerounded copies of inputs
__device__ float g_hs[M_*HID_];     // 16 MB
__device__ float g_wq[HID_*HID_];   // 16 MB
__device__ float g_wk[HID_*KV_];    //  4 MB
__device__ float g_wv[HID_*KV_];    //  4 MB
__device__ float g_wo[HID_*HID_];   // 16 MB

// ---------------------------------------------------------------------------
// Helpers
// ---------------------------------------------------------------------------
__device__ __forceinline__ uint32_t f2tf32(float x) {
    uint32_t r;
    asm("cvt.rna.tf32.f32 %0, %1;" : "=r"(r) : "f"(x));
    return r;
}

__device__ __forceinline__ void mma_tf32(float* c, uint32_t a0, uint32_t a1,
                                         uint32_t a2, uint32_t a3,
                                         uint32_t b0, uint32_t b1) {
    asm volatile(
        "mma.sync.aligned.m16n8k8.row.col.f32.tf32.tf32.f32 "
        "{%0,%1,%2,%3}, {%4,%5,%6,%7}, {%8,%9}, {%0,%1,%2,%3};"
        : "+f"(c[0]), "+f"(c[1]), "+f"(c[2]), "+f"(c[3])
        : "r"(a0), "r"(a1), "r"(a2), "r"(a3), "r"(b0), "r"(b1));
}

__device__ __forceinline__ void cp16(void* smem, const void* g) {
    uint32_t s = (uint32_t)__cvta_generic_to_shared(smem);
    asm volatile("cp.async.cg.shared.global [%0], [%1], 16;" :: "r"(s), "l"(g));
}

__device__ __forceinline__ void ldm_x4(uint32_t* r, uint32_t saddr) {
    asm volatile("ldmatrix.sync.aligned.m8n8.x4.shared.b16 {%0,%1,%2,%3}, [%4];"
        : "=r"(r[0]), "=r"(r[1]), "=r"(r[2]), "=r"(r[3]) : "r"(saddr));
}

// ---------------------------------------------------------------------------
// tf32 pre-rounding pass (elementwise, float4)
// ---------------------------------------------------------------------------
__global__ void cvt_tf32(const float* __restrict__ in, float* __restrict__ out, int n4) {
    int i = blockIdx.x * blockDim.x + threadIdx.x;
    if (i >= n4) return;
    float4 v = ((const float4*)in)[i];
    v.x = __uint_as_float(f2tf32(v.x));
    v.y = __uint_as_float(f2tf32(v.y));
    v.z = __uint_as_float(f2tf32(v.z));
    v.w = __uint_as_float(f2tf32(v.w));
    ((float4*)out)[i] = v;
}

// ---------------------------------------------------------------------------
// TF32 GEMM (inputs pre-rounded): C = A @ B. CTA 128x128x16, 128 thr = 4 warps,
// warp tile 64x64. cp.async double-buffered, ldmatrix A-frags, no in-loop cvt.
// Optional fused RoPE on the output (rope=1: Q/K projections).
// ---------------------------------------------------------------------------
#define BM 128
#define BN 128
#define BK 16
#define ASTRIDE 20    // ldmatrix phase banks (20j)%32 all distinct
#define BSTRIDE 136   // B frag bank (8t+g)%32 all distinct

__device__ __forceinline__ void tgemm_core(const float* __restrict__ A,
                                           const float* __restrict__ Bm,
                                           float* __restrict__ C,
                                           int N, int K, int rope,
                                           const float* __restrict__ cosT,
                                           const float* __restrict__ sinT) {
    __shared__ float As[2][BM][ASTRIDE];
    __shared__ float Bs[2][BK][BSTRIDE];

    const int tid  = threadIdx.x;
    const int warp = tid >> 5;
    const int lane = tid & 31;
    const int g = lane >> 2;
    const int t = lane & 3;
    const int wm = (warp & 1) * 64;
    const int wn = (warp >> 1) * 64;
    const int bm = blockIdx.y * BM;
    const int bn = blockIdx.x * BN;

    const int a_r = tid >> 2;          // +32*i
    const int a_c = (tid & 3) * 4;
    const int b_r = tid >> 5;          // +4*i
    const int b_c = lane * 4;

    // ldmatrix lane->source mapping
    const int lrow = ((lane >> 3) & 1) * 8 + (lane & 7);
    const int lcol = ((lane >> 4) & 1) * 4;
    const uint32_t as_base = (uint32_t)__cvta_generic_to_shared(&As[0][0][0]);

    float acc[4][8][4];
#pragma unroll
    for (int mi = 0; mi < 4; mi++)
#pragma unroll
        for (int ni = 0; ni < 8; ni++)
#pragma unroll
            for (int f = 0; f < 4; f++) acc[mi][ni][f] = 0.f;

#define ISSUE_TILE(buf, k0)                                                   \
    {                                                                         \
        _Pragma("unroll")                                                     \
        for (int i = 0; i < 4; i++) {                                         \
            int r = a_r + 32 * i;                                             \
            cp16(&As[buf][r][a_c], &A[(size_t)(bm + r) * K + (k0) + a_c]);    \
        }                                                                     \
        _Pragma("unroll")                                                     \
        for (int i = 0; i < 4; i++) {                                         \
            int r = b_r + 4 * i;                                              \
            cp16(&Bs[buf][r][b_c], &Bm[(size_t)((k0) + r) * N + bn + b_c]);   \
        }                                                                     \
        asm volatile("cp.async.commit_group;");                               \
    }

    const int NIT = K / BK;
    ISSUE_TILE(0, 0);

    for (int it = 0; it < NIT; it++) {
        const int cur = it & 1;
        if (it + 1 < NIT) {
            ISSUE_TILE(cur ^ 1, (it + 1) * BK);
            asm volatile("cp.async.wait_group 1;");
        } else {
            asm volatile("cp.async.wait_group 0;");
        }
        __syncthreads();

        const uint32_t abuf = as_base + (uint32_t)(cur * BM * ASTRIDE * 4);
#pragma unroll
        for (int kk = 0; kk < BK; kk += 8) {
            uint32_t bf[8][2];
#pragma unroll
            for (int ni = 0; ni < 8; ni++) {
                int n = wn + 8 * ni + g;
                bf[ni][0] = __float_as_uint(Bs[cur][kk + t][n]);
                bf[ni][1] = __float_as_uint(Bs[cur][kk + t + 4][n]);
            }
#pragma unroll
            for (int mi = 0; mi < 4; mi++) {
                uint32_t a[4];
                uint32_t addr = abuf +
                    (uint32_t)(((wm + 16 * mi + lrow) * ASTRIDE + kk + lcol) * 4);
                ldm_x4(a, addr);
#pragma unroll
                for (int ni = 0; ni < 8; ni++)
                    mma_tf32(acc[mi][ni], a[0], a[1], a[2], a[3], bf[ni][0], bf[ni][1]);
            }
        }
        __syncthreads();
    }
#undef ISSUE_TILE

    if (!rope) {
#pragma unroll
        for (int mi = 0; mi < 4; mi++) {
#pragma unroll
            for (int ni = 0; ni < 8; ni++) {
                int r0 = bm + wm + 16 * mi + g;
                int col = bn + wn + 8 * ni + 2 * t;
                *(float2*)&C[(size_t)r0 * N + col] =
                    make_float2(acc[mi][ni][0], acc[mi][ni][1]);
                *(float2*)&C[(size_t)(r0 + 8) * N + col] =
                    make_float2(acc[mi][ni][2], acc[mi][ni][3]);
            }
        }
    } else {
        // Fused RoPE: heads are 64-aligned with warp n-tiles; d in [0,32)
        // lives at ni, d+32 at ni+4.
#pragma unroll
        for (int mi = 0; mi < 4; mi++) {
            int r0 = bm + wm + 16 * mi + g;
            int s0 = r0 & (S_ - 1);
            int s1 = (r0 + 8) & (S_ - 1);
#pragma unroll
            for (int ni = 0; ni < 4; ni++) {
                int col = bn + wn + 8 * ni + 2 * t;
                int d = 8 * ni + 2 * t;          // < 32
                float c0a = cosT[s0 * HD_ + d],     c1a = cosT[s0 * HD_ + d + 1];
                float n0a = sinT[s0 * HD_ + d],     n1a = sinT[s0 * HD_ + d + 1];
                float c0b = cosT[s1 * HD_ + d],     c1b = cosT[s1 * HD_ + d + 1];
                float n0b = sinT[s1 * HD_ + d],     n1b = sinT[s1 * HD_ + d + 1];
                float* lo = acc[mi][ni];
                float* hi = acc[mi][ni + 4];
                float lo0 = lo[0] * c0a - hi[0] * n0a;
                float lo1 = lo[1] * c1a - hi[1] * n1a;
                float hi0 = hi[0] * c0a + lo[0] * n0a;
                float hi1 = hi[1] * c1a + lo[1] * n1a;
                float lo2 = lo[2] * c0b - hi[2] * n0b;
                float lo3 = lo[3] * c1b - hi[3] * n1b;
                float hi2 = hi[2] * c0b + lo[2] * n0b;
                float hi3 = hi[3] * c1b + lo[3] * n1b;
                *(float2*)&C[(size_t)r0 * N + col]            = make_float2(lo0, lo1);
                *(float2*)&C[(size_t)r0 * N + col + 32]       = make_float2(hi0, hi1);
                *(float2*)&C[(size_t)(r0 + 8) * N + col]      = make_float2(lo2, lo3);
                *(float2*)&C[(size_t)(r0 + 8) * N + col + 32] = make_float2(hi2, hi3);
            }
        }
    }
}

__global__ __launch_bounds__(128)
void tgemm_q(const float* __restrict__ A, const float* __restrict__ Bm,
             float* __restrict__ C, int N, int K, int rope,
             const float* __restrict__ cosT, const float* __restrict__ sinT) {
    tgemm_core(A, Bm, C, N, K, rope, cosT, sinT);
}

__global__ __launch_bounds__(128)
void tgemm_kv(const float* __restrict__ A,
              const float* __restrict__ Wk, const float* __restrict__ Wv,
              float* __restrict__ k, float* __restrict__ v, int N, int K,
              const float* __restrict__ cosT, const float* __restrict__ sinT) {
    // z=0: K projection (rope), z=1: V projection (no rope)
    tgemm_core(A, blockIdx.z ? Wv : Wk, blockIdx.z ? v : k, N, K,
               blockIdx.z ? 0 : 1, cosT, sinT);
}

// ---------------------------------------------------------------------------
// Flash attention on tensor cores (unchanged from R14, except the output is
// tf32-prerounded so the O-projection can consume it raw).
// ---------------------------------------------------------------------------
__global__ __launch_bounds__(128)
void flash_mma(const float* __restrict__ q, const float* __restrict__ k,
               const float* __restrict__ v, float* __restrict__ out) {
    __shared__ float KsT[64][40];
    __shared__ float Vs[32][72];
    __shared__ float Ps[64][36];

    const int bh = blockIdx.x;
    const int b = bh / HQ_, h = bh % HQ_;
    const int kvh = h / (HQ_ / HKV_);
    const int q0 = blockIdx.y * 64;
    const int w = threadIdx.x >> 5, lane = threadIdx.x & 31;
    const int g = lane >> 2, t = lane & 3;
    const int wm = w * 16;
    const int r0 = q0 + wm + g, r1 = r0 + 8;

    uint32_t qa[8][4];
#pragma unroll
    for (int ks = 0; ks < 8; ks++) {
        size_t ba0 = (((size_t)(b * S_ + r0)) * HQ_ + h) * HD_ + 8 * ks;
        size_t ba1 = (((size_t)(b * S_ + r1)) * HQ_ + h) * HD_ + 8 * ks;
        qa[ks][0] = f2tf32(q[ba0 + t]);
        qa[ks][1] = f2tf32(q[ba1 + t]);
        qa[ks][2] = f2tf32(q[ba0 + t + 4]);
        qa[ks][3] = f2tf32(q[ba1 + t + 4]);
    }

    float m0 = -1e30f, m1 = -1e30f, l0 = 0.f, l1 = 0.f;
    float o[8][4];
#pragma unroll
    for (int ni = 0; ni < 8; ni++)
#pragma unroll
        for (int f = 0; f < 4; f++) o[ni][f] = 0.f;

    const int ntiles = q0 / 32 + 2;
    for (int tl = 0; tl < ntiles; tl++) {
        const int key0 = tl * 32;
        __syncthreads();
#pragma unroll
        for (int i = threadIdx.x; i < 512; i += 128) {
            int key = i >> 4, d4 = (i & 15) * 4;
            size_t gi = (((size_t)(b * S_ + key0 + key)) * HKV_ + kvh) * HD_ + d4;
            float4 kv = *(const float4*)&k[gi];
            KsT[d4 + 0][key] = __uint_as_float(f2tf32(kv.x));
            KsT[d4 + 1][key] = __uint_as_float(f2tf32(kv.y));
            KsT[d4 + 2][key] = __uint_as_float(f2tf32(kv.z));
            KsT[d4 + 3][key] = __uint_as_float(f2tf32(kv.w));
            float4 vv = *(const float4*)&v[gi];
            float4 vc;
            vc.x = __uint_as_float(f2tf32(vv.x));
            vc.y = __uint_as_float(f2tf32(vv.y));
            vc.z = __uint_as_float(f2tf32(vv.z));
            vc.w = __uint_as_float(f2tf32(vv.w));
            *(float4*)&Vs[key][d4] = vc;
        }
        __syncthreads();

        float s[4][4];
#pragma unroll
        for (int ni = 0; ni < 4; ni++)
#pragma unroll
            for (int f = 0; f < 4; f++) s[ni][f] = 0.f;
#pragma unroll
        for (int ks = 0; ks < 8; ks++) {
#pragma unroll
            for (int ni = 0; ni < 4; ni++) {
                uint32_t b0 = __float_as_uint(KsT[8 * ks + t][8 * ni + g]);
                uint32_t b1 = __float_as_uint(KsT[8 * ks + t + 4][8 * ni + g]);
                mma_tf32(s[ni], qa[ks][0], qa[ks][1], qa[ks][2], qa[ks][3], b0, b1);
            }
        }

        float rm0 = -1e30f, rm1 = -1e30f;
#pragma unroll
        for (int ni = 0; ni < 4; ni++) {
            int c0 = key0 + 8 * ni + 2 * t, c1 = c0 + 1;
            s[ni][0] = (c0 > r0) ? -1e30f : s[ni][0] * 0.125f;
            s[ni][1] = (c1 > r0) ? -1e30f : s[ni][1] * 0.125f;
            s[ni][2] = (c0 > r1) ? -1e30f : s[ni][2] * 0.125f;
            s[ni][3] = (c1 > r1) ? -1e30f : s[ni][3] * 0.125f;
            rm0 = fmaxf(rm0, fmaxf(s[ni][0], s[ni][1]));
            rm1 = fmaxf(rm1, fmaxf(s[ni][2], s[ni][3]));
        }
#pragma unroll
        for (int off = 1; off <= 2; off <<= 1) {
            rm0 = fmaxf(rm0, __shfl_xor_sync(0xFFFFFFFFu, rm0, off));
            rm1 = fmaxf(rm1, __shfl_xor_sync(0xFFFFFFFFu, rm1, off));
        }
        float mn0 = fmaxf(m0, rm0), mn1 = fmaxf(m1, rm1);
        float corr0 = __expf(m0 - mn0), corr1 = __expf(m1 - mn1);
        float p[4][4];
        float ps0 = 0.f, ps1 = 0.f;
#pragma unroll
        for (int ni = 0; ni < 4; ni++) {
            p[ni][0] = __expf(s[ni][0] - mn0);
            p[ni][1] = __expf(s[ni][1] - mn0);
            p[ni][2] = __expf(s[ni][2] - mn1);
            p[ni][3] = __expf(s[ni][3] - mn1);
            ps0 += p[ni][0] + p[ni][1];
            ps1 += p[ni][2] + p[ni][3];
        }
#pragma unroll
        for (int off = 1; off <= 2; off <<= 1) {
            ps0 += __shfl_xor_sync(0xFFFFFFFFu, ps0, off);
            ps1 += __shfl_xor_sync(0xFFFFFFFFu, ps1, off);
        }
        l0 = l0 * corr0 + ps0;
        l1 = l1 * corr1 + ps1;
#pragma unroll
        for (int ni = 0; ni < 8; ni++) {
            o[ni][0] *= corr0; o[ni][1] *= corr0;
            o[ni][2] *= corr1; o[ni][3] *= corr1;
        }
#pragma unroll
        for (int ni = 0; ni < 4; ni++) {
            *(float2*)&Ps[wm + g][8 * ni + 2 * t] = make_float2(
                __uint_as_float(f2tf32(p[ni][0])), __uint_as_float(f2tf32(p[ni][1])));
            *(float2*)&Ps[wm + g + 8][8 * ni + 2 * t] = make_float2(
                __uint_as_float(f2tf32(p[ni][2])), __uint_as_float(f2tf32(p[ni][3])));
        }
        __syncwarp();

#pragma unroll
        for (int ks = 0; ks < 4; ks++) {
            uint32_t a0 = __float_as_uint(Ps[wm + g][8 * ks + t]);
            uint32_t a1 = __float_as_uint(Ps[wm + g + 8][8 * ks + t]);
            uint32_t a2 = __float_as_uint(Ps[wm + g][8 * ks + t + 4]);
            uint32_t a3 = __float_as_uint(Ps[wm + g + 8][8 * ks + t + 4]);
#pragma unroll
            for (int ni = 0; ni < 8; ni++) {
                uint32_t b0 = __float_as_uint(Vs[8 * ks + t][8 * ni + g]);
                uint32_t b1 = __float_as_uint(Vs[8 * ks + t + 4][8 * ni + g]);
                mma_tf32(o[ni], a0, a1, a2, a3, b0, b1);
            }
        }
        m0 = mn0; m1 = mn1;
    }

    // Write output tf32-prerounded (consumed raw by the O-projection)
    float inv0 = 1.f / l0, inv1 = 1.f / l1;
#pragma unroll
    for (int ni = 0; ni < 8; ni++) {
        int col = 8 * ni + 2 * t;
        *(float2*)&out[(((size_t)(b * S_ + r0)) * HQ_ + h) * HD_ + col] =
            make_float2(__uint_as_float(f2tf32(o[ni][0] * inv0)),
                        __uint_as_float(f2tf32(o[ni][1] * inv0)));
        *(float2*)&out[(((size_t)(b * S_ + r1)) * HQ_ + h) * HD_ + col] =
            make_float2(__uint_as_float(f2tf32(o[ni][2] * inv1)),
                        __uint_as_float(f2tf32(o[ni][3] * inv1)));
    }
}

// ---------------------------------------------------------------------------
extern "C" void kernel_launch(void* const* d_in, const int* in_sizes, int n_in,
                              void* d_out, int out_size) {
    const float* hs   = (const float*)d_in[0];
    const float* cosT = (const float*)d_in[1];
    const float* sinT = (const float*)d_in[2];
    const float* Wq   = (const float*)d_in[3];
    const float* Wk   = (const float*)d_in[4];
    const float* Wv   = (const float*)d_in[5];
    const float* Wo   = (const float*)d_in[6];
    float* out = (float*)d_out;

    float *q, *k, *v, *att, *phs, *pwq, *pwk, *pwv, *pwo;
    cudaGetSymbolAddress((void**)&q,   g_q);
    cudaGetSymbolAddress((void**)&k,   g_k);
    cudaGetSymbolAddress((void**)&v,   g_v);
    cudaGetSymbolAddress((void**)&att, g_att);
    cudaGetSymbolAddress((void**)&phs, g_hs);
    cudaGetSymbolAddress((void**)&pwq, g_wq);
    cudaGetSymbolAddress((void**)&pwk, g_wk);
    cudaGetSymbolAddress((void**)&pwv, g_wv);
    cudaGetSymbolAddress((void**)&pwo, g_wo);

    // tf32 pre-rounding of GEMM inputs (makes in-loop cvt unnecessary,
    // numerics identical to converting at consume time)
    cvt_tf32<<<(M_*HID_/4 + 255)/256, 256>>>(hs, phs, M_*HID_/4);
    cvt_tf32<<<(HID_*HID_/4 + 255)/256, 256>>>(Wq, pwq, HID_*HID_/4);
    cvt_tf32<<<(HID_*KV_/4 + 255)/256, 256>>>(Wk, pwk, HID_*KV_/4);
    cvt_tf32<<<(HID_*KV_/4 + 255)/256, 256>>>(Wv, pwv, HID_*KV_/4);
    cvt_tf32<<<(HID_*HID_/4 + 255)/256, 256>>>(Wo, pwo, HID_*HID_/4);

    dim3 blk(128);
    // Q projection with fused RoPE
    tgemm_q<<<dim3(HID_ / BN, M_ / BM), blk>>>(phs, pwq, q, HID_, HID_, 1, cosT, sinT);
    // K (rope) + V projections merged
    tgemm_kv<<<dim3(KV_ / BN, M_ / BM, 2), blk>>>(phs, pwk, pwv, k, v, KV_, HID_, cosT, sinT);

    // Attention (tensor-core flash)
    flash_mma<<<dim3(B_ * HQ_, S_ / 64), blk>>>(q, k, v, att);

    // Output projection (att already tf32-rounded by flash)
    tgemm_q<<<dim3(HID_ / BN, M_ / BM), blk>>>(att, pwo, out, HID_, HID_, 0, cosT, sinT);
}

// round 17
// speedup vs baseline: 5.8177x; 1.1374x over previous
#include <cuda_runtime.h>
#include <cuda_bf16.h>
#include <cstdint>

// Problem dims
#define B_   2
#define S_   1024
#define HID_ 2048
#define HQ_  32
#define HKV_ 8
#define HD_  64
#define KV_  (HKV_*HD_)   // 512
#define M_   (B_*S_)      // 2048

// Scratch (device globals — no allocation allowed)
__device__ float g_q[M_*HID_];      // 16 MB
__device__ float g_k[M_*KV_];       //  4 MB
__device__ float g_v[M_*KV_];       //  4 MB
__device__ float g_att[M_*HID_];    // 16 MB

// ---------------------------------------------------------------------------
// Helpers
// ---------------------------------------------------------------------------
__device__ __forceinline__ uint32_t f2tf32(float x) {
    uint32_t r;
    asm("cvt.rna.tf32.f32 %0, %1;" : "=r"(r) : "f"(x));
    return r;
}

__device__ __forceinline__ void mma_tf32(float* c, uint32_t a0, uint32_t a1,
                                         uint32_t a2, uint32_t a3,
                                         uint32_t b0, uint32_t b1) {
    asm volatile(
        "mma.sync.aligned.m16n8k8.row.col.f32.tf32.tf32.f32 "
        "{%0,%1,%2,%3}, {%4,%5,%6,%7}, {%8,%9}, {%0,%1,%2,%3};"
        : "+f"(c[0]), "+f"(c[1]), "+f"(c[2]), "+f"(c[3])
        : "r"(a0), "r"(a1), "r"(a2), "r"(a3), "r"(b0), "r"(b1));
}

__device__ __forceinline__ void cp16(void* smem, const void* g) {
    uint32_t s = (uint32_t)__cvta_generic_to_shared(smem);
    asm volatile("cp.async.cg.shared.global [%0], [%1], 16;" :: "r"(s), "l"(g));
}

__device__ __forceinline__ void ldm_x4(uint32_t* r, uint32_t saddr) {
    asm volatile("ldmatrix.sync.aligned.m8n8.x4.shared.b16 {%0,%1,%2,%3}, [%4];"
        : "=r"(r[0]), "=r"(r[1]), "=r"(r[2]), "=r"(r[3]) : "r"(saddr));
}

// ---------------------------------------------------------------------------
// TF32 GEMM core: C = A @ B (fp32 in/out, tf32 rounding at consume).
// CTA 128x128x16, 128 thr = 4 warps, warp tile 64x64. cp.async double-buffer,
// ldmatrix A-frags. Optional fused RoPE epilogue (Q/K projections).
// ---------------------------------------------------------------------------
#define BM 128
#define BN 128
#define BK 16
#define ASTRIDE 20    // ldmatrix phase banks (20j)%32 all distinct
#define BSTRIDE 136   // B frag bank (8t+g)%32 all distinct

__device__ __forceinline__ void tgemm_core(const float* __restrict__ A,
                                           const float* __restrict__ Bm,
                                           float* __restrict__ C,
                                           int N, int K, int bn, int rope,
                                           const float* __restrict__ cosT,
                                           const float* __restrict__ sinT) {
    __shared__ float As[2][BM][ASTRIDE];
    __shared__ float Bs[2][BK][BSTRIDE];

    const int tid  = threadIdx.x;
    const int warp = tid >> 5;
    const int lane = tid & 31;
    const int g = lane >> 2;
    const int t = lane & 3;
    const int wm = (warp & 1) * 64;
    const int wn = (warp >> 1) * 64;
    const int bm = blockIdx.y * BM;

    const int a_r = tid >> 2;          // +32*i
    const int a_c = (tid & 3) * 4;
    const int b_r = tid >> 5;          // +4*i
    const int b_c = lane * 4;

    // ldmatrix lane->source mapping
    const int lrow = ((lane >> 3) & 1) * 8 + (lane & 7);
    const int lcol = ((lane >> 4) & 1) * 4;
    const uint32_t as_base = (uint32_t)__cvta_generic_to_shared(&As[0][0][0]);

    float acc[4][8][4];
#pragma unroll
    for (int mi = 0; mi < 4; mi++)
#pragma unroll
        for (int ni = 0; ni < 8; ni++)
#pragma unroll
            for (int f = 0; f < 4; f++) acc[mi][ni][f] = 0.f;

#define ISSUE_TILE(buf, k0)                                                   \
    {                                                                         \
        _Pragma("unroll")                                                     \
        for (int i = 0; i < 4; i++) {                                         \
            int r = a_r + 32 * i;                                             \
            cp16(&As[buf][r][a_c], &A[(size_t)(bm + r) * K + (k0) + a_c]);    \
        }                                                                     \
        _Pragma("unroll")                                                     \
        for (int i = 0; i < 4; i++) {                                         \
            int r = b_r + 4 * i;                                              \
            cp16(&Bs[buf][r][b_c], &Bm[(size_t)((k0) + r) * N + bn + b_c]);   \
        }                                                                     \
        asm volatile("cp.async.commit_group;");                               \
    }

    const int NIT = K / BK;
    ISSUE_TILE(0, 0);

    for (int it = 0; it < NIT; it++) {
        const int cur = it & 1;
        if (it + 1 < NIT) {
            ISSUE_TILE(cur ^ 1, (it + 1) * BK);
            asm volatile("cp.async.wait_group 1;");
        } else {
            asm volatile("cp.async.wait_group 0;");
        }
        __syncthreads();

        const uint32_t abuf = as_base + (uint32_t)(cur * BM * ASTRIDE * 4);
#pragma unroll
        for (int kk = 0; kk < BK; kk += 8) {
            uint32_t bf[8][2];
#pragma unroll
            for (int ni = 0; ni < 8; ni++) {
                int n = wn + 8 * ni + g;
                bf[ni][0] = f2tf32(Bs[cur][kk + t][n]);
                bf[ni][1] = f2tf32(Bs[cur][kk + t + 4][n]);
            }
#pragma unroll
            for (int mi = 0; mi < 4; mi++) {
                uint32_t a[4];
                uint32_t addr = abuf +
                    (uint32_t)(((wm + 16 * mi + lrow) * ASTRIDE + kk + lcol) * 4);
                ldm_x4(a, addr);
#pragma unroll
                for (int j = 0; j < 4; j++)
                    a[j] = f2tf32(__uint_as_float(a[j]));
#pragma unroll
                for (int ni = 0; ni < 8; ni++)
                    mma_tf32(acc[mi][ni], a[0], a[1], a[2], a[3], bf[ni][0], bf[ni][1]);
            }
        }
        __syncthreads();
    }
#undef ISSUE_TILE

    if (!rope) {
#pragma unroll
        for (int mi = 0; mi < 4; mi++) {
#pragma unroll
            for (int ni = 0; ni < 8; ni++) {
                int r0 = bm + wm + 16 * mi + g;
                int col = bn + wn + 8 * ni + 2 * t;
                *(float2*)&C[(size_t)r0 * N + col] =
                    make_float2(acc[mi][ni][0], acc[mi][ni][1]);
                *(float2*)&C[(size_t)(r0 + 8) * N + col] =
                    make_float2(acc[mi][ni][2], acc[mi][ni][3]);
            }
        }
    } else {
        // Fused RoPE: warp n-tile (64 wide) = exactly one head; d in [0,32)
        // at ni, d+32 at ni+4.
#pragma unroll
        for (int mi = 0; mi < 4; mi++) {
            int r0 = bm + wm + 16 * mi + g;
            int s0 = r0 & (S_ - 1);
            int s1 = (r0 + 8) & (S_ - 1);
#pragma unroll
            for (int ni = 0; ni < 4; ni++) {
                int col = bn + wn + 8 * ni + 2 * t;
                int d = 8 * ni + 2 * t;          // < 32
                float c0a = cosT[s0 * HD_ + d],     c1a = cosT[s0 * HD_ + d + 1];
                float n0a = sinT[s0 * HD_ + d],     n1a = sinT[s0 * HD_ + d + 1];
                float c0b = cosT[s1 * HD_ + d],     c1b = cosT[s1 * HD_ + d + 1];
                float n0b = sinT[s1 * HD_ + d],     n1b = sinT[s1 * HD_ + d + 1];
                float* lo = acc[mi][ni];
                float* hi = acc[mi][ni + 4];
                float lo0 = lo[0] * c0a - hi[0] * n0a;
                float lo1 = lo[1] * c1a - hi[1] * n1a;
                float hi0 = hi[0] * c0a + lo[0] * n0a;
                float hi1 = hi[1] * c1a + lo[1] * n1a;
                float lo2 = lo[2] * c0b - hi[2] * n0b;
                float lo3 = lo[3] * c1b - hi[3] * n1b;
                float hi2 = hi[2] * c0b + lo[2] * n0b;
                float hi3 = hi[3] * c1b + lo[3] * n1b;
                *(float2*)&C[(size_t)r0 * N + col]            = make_float2(lo0, lo1);
                *(float2*)&C[(size_t)r0 * N + col + 32]       = make_float2(hi0, hi1);
                *(float2*)&C[(size_t)(r0 + 8) * N + col]      = make_float2(lo2, lo3);
                *(float2*)&C[(size_t)(r0 + 8) * N + col + 32] = make_float2(hi2, hi3);
            }
        }
    }
}

// Merged Q+K+V projection: 24 column-tiles x 16 row-tiles = 384 CTAs.
// bx<16: Q (rope), bx 16-19: K (rope), bx 20-23: V.
__global__ __launch_bounds__(128)
void tgemm_qkv(const float* __restrict__ hs,
               const float* __restrict__ Wq, const float* __restrict__ Wk,
               const float* __restrict__ Wv,
               float* __restrict__ q, float* __restrict__ k, float* __restrict__ v,
               const float* __restrict__ cosT, const float* __restrict__ sinT) {
    const int bx = blockIdx.x;
    const float* W;
    float* C;
    int N, bn, rope;
    if (bx < 16)      { W = Wq; C = q; N = HID_; bn = bx * 128;        rope = 1; }
    else if (bx < 20) { W = Wk; C = k; N = KV_;  bn = (bx - 16) * 128; rope = 1; }
    else              { W = Wv; C = v; N = KV_;  bn = (bx - 20) * 128; rope = 0; }
    tgemm_core(hs, W, C, N, HID_, bn, rope, cosT, sinT);
}

// Plain GEMM (output projection)
__global__ __launch_bounds__(128)
void tgemm_o(const float* __restrict__ A, const float* __restrict__ Bm,
             float* __restrict__ C, int N, int K) {
    tgemm_core(A, Bm, C, N, K, blockIdx.x * BN, 0, nullptr, nullptr);
}

// ---------------------------------------------------------------------------
// Flash attention on tensor cores (tf32 mma). CTA: 64 q rows, one (b,h),
// 128 threads = 4 warps (each m16). KV tiles of 32 keys.
// ---------------------------------------------------------------------------
__global__ __launch_bounds__(128)
void flash_mma(const float* __restrict__ q, const float* __restrict__ k,
               const float* __restrict__ v, float* __restrict__ out) {
    __shared__ float KsT[64][40];
    __shared__ float Vs[32][72];
    __shared__ float Ps[64][36];

    const int bh = blockIdx.x;
    const int b = bh / HQ_, h = bh % HQ_;
    const int kvh = h / (HQ_ / HKV_);
    const int q0 = blockIdx.y * 64;
    const int w = threadIdx.x >> 5, lane = threadIdx.x & 31;
    const int g = lane >> 2, t = lane & 3;
    const int wm = w * 16;
    const int r0 = q0 + wm + g, r1 = r0 + 8;

    uint32_t qa[8][4];
#pragma unroll
    for (int ks = 0; ks < 8; ks++) {
        size_t ba0 = (((size_t)(b * S_ + r0)) * HQ_ + h) * HD_ + 8 * ks;
        size_t ba1 = (((size_t)(b * S_ + r1)) * HQ_ + h) * HD_ + 8 * ks;
        qa[ks][0] = f2tf32(q[ba0 + t]);
        qa[ks][1] = f2tf32(q[ba1 + t]);
        qa[ks][2] = f2tf32(q[ba0 + t + 4]);
        qa[ks][3] = f2tf32(q[ba1 + t + 4]);
    }

    float m0 = -1e30f, m1 = -1e30f, l0 = 0.f, l1 = 0.f;
    float o[8][4];
#pragma unroll
    for (int ni = 0; ni < 8; ni++)
#pragma unroll
        for (int f = 0; f < 4; f++) o[ni][f] = 0.f;

    const int ntiles = q0 / 32 + 2;
    for (int tl = 0; tl < ntiles; tl++) {
        const int key0 = tl * 32;
        __syncthreads();
#pragma unroll
        for (int i = threadIdx.x; i < 512; i += 128) {
            int key = i >> 4, d4 = (i & 15) * 4;
            size_t gi = (((size_t)(b * S_ + key0 + key)) * HKV_ + kvh) * HD_ + d4;
            float4 kv = *(const float4*)&k[gi];
            KsT[d4 + 0][key] = __uint_as_float(f2tf32(kv.x));
            KsT[d4 + 1][key] = __uint_as_float(f2tf32(kv.y));
            KsT[d4 + 2][key] = __uint_as_float(f2tf32(kv.z));
            KsT[d4 + 3][key] = __uint_as_float(f2tf32(kv.w));
            float4 vv = *(const float4*)&v[gi];
            float4 vc;
            vc.x = __uint_as_float(f2tf32(vv.x));
            vc.y = __uint_as_float(f2tf32(vv.y));
            vc.z = __uint_as_float(f2tf32(vv.z));
            vc.w = __uint_as_float(f2tf32(vv.w));
            *(float4*)&Vs[key][d4] = vc;
        }
        __syncthreads();

        float s[4][4];
#pragma unroll
        for (int ni = 0; ni < 4; ni++)
#pragma unroll
            for (int f = 0; f < 4; f++) s[ni][f] = 0.f;
#pragma unroll
        for (int ks = 0; ks < 8; ks++) {
#pragma unroll
            for (int ni = 0; ni < 4; ni++) {
                uint32_t b0 = __float_as_uint(KsT[8 * ks + t][8 * ni + g]);
                uint32_t b1 = __float_as_uint(KsT[8 * ks + t + 4][8 * ni + g]);
                mma_tf32(s[ni], qa[ks][0], qa[ks][1], qa[ks][2], qa[ks][3], b0, b1);
            }
        }

        float rm0 = -1e30f, rm1 = -1e30f;
#pragma unroll
        for (int ni = 0; ni < 4; ni++) {
            int c0 = key0 + 8 * ni + 2 * t, c1 = c0 + 1;
            s[ni][0] = (c0 > r0) ? -1e30f : s[ni][0] * 0.125f;
            s[ni][1] = (c1 > r0) ? -1e30f : s[ni][1] * 0.125f;
            s[ni][2] = (c0 > r1) ? -1e30f : s[ni][2] * 0.125f;
            s[ni][3] = (c1 > r1) ? -1e30f : s[ni][3] * 0.125f;
            rm0 = fmaxf(rm0, fmaxf(s[ni][0], s[ni][1]));
            rm1 = fmaxf(rm1, fmaxf(s[ni][2], s[ni][3]));
        }
#pragma unroll
        for (int off = 1; off <= 2; off <<= 1) {
            rm0 = fmaxf(rm0, __shfl_xor_sync(0xFFFFFFFFu, rm0, off));
            rm1 = fmaxf(rm1, __shfl_xor_sync(0xFFFFFFFFu, rm1, off));
        }
        float mn0 = fmaxf(m0, rm0), mn1 = fmaxf(m1, rm1);
        float corr0 = __expf(m0 - mn0), corr1 = __expf(m1 - mn1);
        float p[4][4];
        float ps0 = 0.f, ps1 = 0.f;
#pragma unroll
        for (int ni = 0; ni < 4; ni++) {
            p[ni][0] = __expf(s[ni][0] - mn0);
            p[ni][1] = __expf(s[ni][1] - mn0);
            p[ni][2] = __expf(s[ni][2] - mn1);
            p[ni][3] = __expf(s[ni][3] - mn1);
            ps0 += p[ni][0] + p[ni][1];
            ps1 += p[ni][2] + p[ni][3];
        }
#pragma unroll
        for (int off = 1; off <= 2; off <<= 1) {
            ps0 += __shfl_xor_sync(0xFFFFFFFFu, ps0, off);
            ps1 += __shfl_xor_sync(0xFFFFFFFFu, ps1, off);
        }
        l0 = l0 * corr0 + ps0;
        l1 = l1 * corr1 + ps1;
#pragma unroll
        for (int ni = 0; ni < 8; ni++) {
            o[ni][0] *= corr0; o[ni][1] *= corr0;
            o[ni][2] *= corr1; o[ni][3] *= corr1;
        }
#pragma unroll
        for (int ni = 0; ni < 4; ni++) {
            *(float2*)&Ps[wm + g][8 * ni + 2 * t] = make_float2(
                __uint_as_float(f2tf32(p[ni][0])), __uint_as_float(f2tf32(p[ni][1])));
            *(float2*)&Ps[wm + g + 8][8 * ni + 2 * t] = make_float2(
                __uint_as_float(f2tf32(p[ni][2])), __uint_as_float(f2tf32(p[ni][3])));
        }
        __syncwarp();

#pragma unroll
        for (int ks = 0; ks < 4; ks++) {
            uint32_t a0 = __float_as_uint(Ps[wm + g][8 * ks + t]);
            uint32_t a1 = __float_as_uint(Ps[wm + g + 8][8 * ks + t]);
            uint32_t a2 = __float_as_uint(Ps[wm + g][8 * ks + t + 4]);
            uint32_t a3 = __float_as_uint(Ps[wm + g + 8][8 * ks + t + 4]);
#pragma unroll
            for (int ni = 0; ni < 8; ni++) {
                uint32_t b0 = __float_as_uint(Vs[8 * ks + t][8 * ni + g]);
                uint32_t b1 = __float_as_uint(Vs[8 * ks + t + 4][8 * ni + g]);
                mma_tf32(o[ni], a0, a1, a2, a3, b0, b1);
            }
        }
        m0 = mn0; m1 = mn1;
    }

    float inv0 = 1.f / l0, inv1 = 1.f / l1;
#pragma unroll
    for (int ni = 0; ni < 8; ni++) {
        int col = 8 * ni + 2 * t;
        *(float2*)&out[(((size_t)(b * S_ + r0)) * HQ_ + h) * HD_ + col] =
            make_float2(o[ni][0] * inv0, o[ni][1] * inv0);
        *(float2*)&out[(((size_t)(b * S_ + r1)) * HQ_ + h) * HD_ + col] =
            make_float2(o[ni][2] * inv1, o[ni][3] * inv1);
    }
}

// ---------------------------------------------------------------------------
extern "C" void kernel_launch(void* const* d_in, const int* in_sizes, int n_in,
                              void* d_out, int out_size) {
    const float* hs   = (const float*)d_in[0];
    const float* cosT = (const float*)d_in[1];
    const float* sinT = (const float*)d_in[2];
    const float* Wq   = (const float*)d_in[3];
    const float* Wk   = (const float*)d_in[4];
    const float* Wv   = (const float*)d_in[5];
    const float* Wo   = (const float*)d_in[6];
    float* out = (float*)d_out;

    float *q, *k, *v, *att;
    cudaGetSymbolAddress((void**)&q,   g_q);
    cudaGetSymbolAddress((void**)&k,   g_k);
    cudaGetSymbolAddress((void**)&v,   g_v);
    cudaGetSymbolAddress((void**)&att, g_att);

    dim3 blk(128);
    // Q+K+V projections in one launch (384 CTAs), RoPE fused
    tgemm_qkv<<<dim3(24, M_ / BM), blk>>>(hs, Wq, Wk, Wv, q, k, v, cosT, sinT);

    // Attention (tensor-core flash)
    flash_mma<<<dim3(B_ * HQ_, S_ / 64), blk>>>(q, k, v, att);

    // Output projection
    tgemm_o<<<dim3(HID_ / BN, M_ / BM), blk>>>(att, Wo, out, HID_, HID_);
}